// round 11
// baseline (speedup 1.0000x reference)
#include <cuda_runtime.h>
#include <cuda.h>
#include <cuda_fp16.h>
#include <cuda_fp8.h>

// 2-layer LSTM LM, B=32,S=512,H=1024,V=32000.
// fp8 weights resident in smem, fp8 activations via TMA (8-buffer pipeline:
// independent K-half prefetched across steps, dependent K-half overlapped
// with independent compute), fp8 mma.sync.m16n8k32, per-CTA release flags.
#define B_   32
#define S_   512
#define H_   1024
#define V_   32000
#define GPL  64
#define HSLOT 32768

__device__ unsigned char g_W0[(size_t)4096 * 2048];       // fp8 e4m3 x16, [r][k]
__device__ unsigned char g_W1[(size_t)4096 * 2048];
__device__ unsigned char g_emb[(size_t)S_ * HSLOT];       // fp8 x64, [t*32+b][k]
__device__ unsigned char g_h0[(size_t)(S_ + 1) * HSLOT];  // fp8 x64
__device__ unsigned char g_h1[(size_t)(S_ + 1) * HSLOT];
__device__ unsigned g_flags0[GPL];
__device__ unsigned g_flags1[GPL];

struct Sm {
    unsigned char A[64][2064];       // 132096 B resident fp8 weights
    unsigned char Bt[8][8192];       //  65536 B: 8 chunk buffers (2 SW128 boxes each)
    float         z[4][16][36];      //   9216 B gate staging
    unsigned char hst[32][16];       //    512 B h staging
    unsigned long long mbar[8];
};                                   // 207424 B -> 1 CTA/SM

// ------------------------------ helpers -------------------------------------
__device__ __forceinline__ unsigned smem_u32(const void* p) {
    return (unsigned)__cvta_generic_to_shared(p);
}
__device__ __forceinline__ void cp16(void* dst, const void* src) {
    unsigned d = smem_u32(dst);
    asm volatile("cp.async.cg.shared.global [%0], [%1], 16;\n" :: "r"(d), "l"(src) : "memory");
}
__device__ __forceinline__ unsigned ld_acq(const unsigned* p) {
    unsigned v;
    asm volatile("ld.acquire.gpu.global.u32 %0, [%1];" : "=r"(v) : "l"(p) : "memory");
    return v;
}
__device__ __forceinline__ void st_rel(unsigned* p, unsigned v) {
    asm volatile("st.release.gpu.global.u32 [%0], %1;" :: "l"(p), "r"(v) : "memory");
}
__device__ __forceinline__ void mbar_init(unsigned a, unsigned c) {
    asm volatile("mbarrier.init.shared.b64 [%0], %1;" :: "r"(a), "r"(c) : "memory");
}
__device__ __forceinline__ void mbar_expect(unsigned a, unsigned bytes) {
    asm volatile("mbarrier.arrive.expect_tx.shared.b64 _, [%0], %1;" :: "r"(a), "r"(bytes) : "memory");
}
__device__ __forceinline__ void mbar_wait(unsigned a, unsigned ph) {
    asm volatile(
        "{\n\t.reg .pred P;\n"
        "W%=:\n\t"
        "mbarrier.try_wait.parity.acquire.cta.shared::cta.b64 P, [%0], %1, 0x989680;\n\t"
        "@!P bra W%=;\n\t}"
        :: "r"(a), "r"(ph) : "memory");
}
__device__ __forceinline__ void tma2d(unsigned dst, const CUtensorMap* m, int x, int y,
                                      unsigned mb) {
    asm volatile(
        "cp.async.bulk.tensor.2d.shared::cta.global.tile.mbarrier::complete_tx::bytes "
        "[%0], [%1, {%2, %3}], [%4];"
        :: "r"(dst), "l"(m), "r"(x), "r"(y), "r"(mb) : "memory");
}
// issue 4 chunks (one K-half of one source row-block) into bufs [bufBase..bufBase+3]
__device__ __forceinline__ void issue4(const CUtensorMap* m, int y, unsigned btAddr,
                                       unsigned mbAddr, int bufBase) {
    #pragma unroll
    for (int i = 0; i < 4; ++i) {
        const unsigned mb = mbAddr + (unsigned)(bufBase + i) * 8;
        mbar_expect(mb, 8192u);
        const unsigned d = btAddr + (unsigned)(bufBase + i) * 8192;
        const int x = i * 256;
        tma2d(d, m, x, y, mb);
        tma2d(d + 4096, m, x + 128, y, mb);
    }
}

// ------------------------------- prep ---------------------------------------
__global__ void prep_weights(const float* __restrict__ Wx, const float* __restrict__ Wh,
                             int layer) {
    unsigned char* __restrict__ W = layer ? g_W1 : g_W0;
    const size_t n = (size_t)4096 * 2048;
    for (size_t idx = (size_t)blockIdx.x * blockDim.x + threadIdx.x; idx < n;
         idx += (size_t)gridDim.x * blockDim.x) {
        int r = (int)(idx >> 11);
        int k = (int)(idx & 2047);
        int cgp = r >> 6, rem = r & 63;
        int gate = rem >> 4, uu = rem & 15;
        int j = gate * H_ + cgp * 16 + uu;
        float v = (k < H_) ? Wx[(size_t)k * 4096 + j]
                           : Wh[(size_t)(k - H_) * 4096 + j];
        W[idx] = (unsigned char)__nv_cvt_float_to_fp8(v * 16.f, __NV_SATFINITE, __NV_E4M3);
    }
}

__global__ void prep_embed(const int* __restrict__ x, const float* __restrict__ emb) {
    const size_t n = (size_t)S_ * HSLOT;
    for (size_t idx = (size_t)blockIdx.x * blockDim.x + threadIdx.x; idx < n;
         idx += (size_t)gridDim.x * blockDim.x) {
        int t   = (int)(idx >> 15);
        int rem = (int)(idx & 32767);
        int b   = rem >> 10;
        int k   = rem & 1023;
        float v = emb[(size_t)x[b * S_ + t] * H_ + k];
        g_emb[idx] = (unsigned char)__nv_cvt_float_to_fp8(v * 64.f, __NV_SATFINITE, __NV_E4M3);
    }
}

__global__ void prep_init() {
    for (int i = blockIdx.x * blockDim.x + threadIdx.x; i < HSLOT;
         i += gridDim.x * blockDim.x) {
        g_h0[i] = 0;
        g_h1[i] = 0;
    }
    if (blockIdx.x == 0 && threadIdx.x < GPL) {
        g_flags0[threadIdx.x] = 0u;
        g_flags1[threadIdx.x] = 0u;
    }
}

// --------------------------- persistent LSTM --------------------------------
__global__ void __launch_bounds__(256, 1)
lstm_persistent(const __grid_constant__ CUtensorMap mE,
                const __grid_constant__ CUtensorMap mH0,
                const __grid_constant__ CUtensorMap mH1,
                const float* __restrict__ bias0, const float* __restrict__ bias1) {
    extern __shared__ __align__(1024) char smem_raw[];
    Sm* S = reinterpret_cast<Sm*>(smem_raw);

    const int tid  = threadIdx.x;
    const int lane = tid & 31;
    const int w    = tid >> 5;
    const int g    = w >> 1;                 // gate 0..3
    const int nh   = w & 1;                  // batch half
    const bool l1  = (blockIdx.x >= GPL);
    const int cg   = l1 ? (blockIdx.x - GPL) : blockIdx.x;

    const unsigned char* __restrict__ Wg = (l1 ? g_W1 : g_W0) + (size_t)cg * 64 * 2048;
    const float* __restrict__ bias = l1 ? bias1 : bias0;
    unsigned char* hout = l1 ? g_h1 : g_h0;
    unsigned* myFlag = (l1 ? g_flags1 : g_flags0) + cg;

    // ---- resident fp8 weights (once) ----
    #pragma unroll
    for (int m = 0; m < 32; ++m) {
        int u   = tid + (m << 8);
        int row = u >> 7;
        int off = (u & 127) << 4;
        cp16(&S->A[row][off], Wg + (size_t)row * 2048 + off);
    }
    asm volatile("cp.async.commit_group;\ncp.async.wait_group 0;\n" ::: "memory");

    const unsigned mbAddr = smem_u32(&S->mbar[0]);
    const unsigned btAddr = smem_u32(&S->Bt[0][0]);
    if (tid == 0) {
        #pragma unroll
        for (int i = 0; i < 8; ++i) mbar_init(mbAddr + i * 8, 1);
    }
    asm volatile("fence.proxy.async.shared::cta;" ::: "memory");
    __syncthreads();

    // ---- A ldmatrix addressing (fp8 m16n8k32 fragments) ----
    const unsigned aBase = smem_u32(
        &S->A[g * 16 + ((lane >> 3) & 1) * 8 + (lane & 7)][(lane >> 4) * 16]);
    // ---- B (activations, SW128 boxes [32 rows][128 cols]) ----
    const int b_row = nh * 16 + ((lane >> 4) & 1) * 8 + (lane & 7);
    const unsigned k16  = (lane >> 3) & 1;
    const unsigned xorv = (unsigned)(b_row & 7);
    const unsigned rowOff = (unsigned)b_row * 128;

    // ---- cell ownership ----
    const int u_loc = tid >> 4;
    const int u_g   = cg * 16 + u_loc;
    const int bb    = (tid & 15) << 1;
    const float bi  = bias[u_g];
    const float bf_ = bias[H_ + u_g];
    const float bg_ = bias[2 * H_ + u_g];
    const float bo_ = bias[3 * H_ + u_g];
    float c_st[2] = {0.f, 0.f};

    // ---- prologue: layer0 prefetches emb[0] (no dependencies) ----
    if (!l1 && tid == 0) issue4(&mE, 0, btAddr, mbAddr, 0);

    for (int t = 0; t < S_; ++t) {
        const unsigned par = (unsigned)t & 1u;

        if (!l1) {
            // own-layer flags gate dep source h0[t]; trivially near-satisfied
            if (tid < GPL) {
                const unsigned tgt = (unsigned)t;
                while (ld_acq(&g_flags0[tid]) < tgt) __nanosleep(16);
            }
            __syncthreads();
            if (tid == 0) issue4(&mH0, t * 32, btAddr, mbAddr, 4);   // dep under indep compute
        } else {
            // own-layer flags gate indep source h1[t]
            if (tid < GPL) {
                const unsigned tgt = (unsigned)t;
                while (ld_acq(&g_flags1[tid]) < tgt) __nanosleep(16);
            }
            __syncthreads();
            if (tid == 0) issue4(&mH1, t * 32, btAddr, mbAddr, 0);
            // cross-layer wait overlaps indep TMA flight
            if (tid < GPL) {
                const unsigned tgt = (unsigned)(t + 1);
                while (ld_acq(&g_flags0[tid]) < tgt) __nanosleep(16);
            }
            __syncthreads();
            if (tid == 0) issue4(&mH0, (t + 1) * 32, btAddr, mbAddr, 4);
        }

        float acc[2][4] = {{0.f, 0.f, 0.f, 0.f}, {0.f, 0.f, 0.f, 0.f}};

        // ---- independent K-half: bufs 0..3 ----
        #pragma unroll
        for (int i = 0; i < 4; ++i) {
            mbar_wait(mbAddr + i * 8, par);
            const int cc = l1 ? (4 + i) : i;          // weight K-chunk index
            const unsigned aA   = aBase + cc * 256;
            const unsigned bufB = btAddr + i * 8192 + rowOff;
            #pragma unroll
            for (int p = 0; p < 8; ++p) {
                unsigned a0, a1, a2, a3;
                asm volatile("ldmatrix.sync.aligned.m8n8.x4.shared.b16 {%0,%1,%2,%3}, [%4];\n"
                             : "=r"(a0), "=r"(a1), "=r"(a2), "=r"(a3) : "r"(aA + p * 32));
                const unsigned tt = 2u * p + k16;
                const unsigned bA = bufB + (tt >> 3) * 4096 + ((tt & 7) ^ xorv) * 16;
                unsigned b0, b1, b2, b3;
                asm volatile("ldmatrix.sync.aligned.m8n8.x4.shared.b16 {%0,%1,%2,%3}, [%4];\n"
                             : "=r"(b0), "=r"(b1), "=r"(b2), "=r"(b3) : "r"(bA));
                asm volatile("mma.sync.aligned.m16n8k32.row.col.f32.e4m3.e4m3.f32 "
                             "{%0,%1,%2,%3}, {%4,%5,%6,%7}, {%8,%9}, {%0,%1,%2,%3};\n"
                             : "+f"(acc[0][0]), "+f"(acc[0][1]), "+f"(acc[0][2]), "+f"(acc[0][3])
                             : "r"(a0), "r"(a1), "r"(a2), "r"(a3), "r"(b0), "r"(b1));
                asm volatile("mma.sync.aligned.m16n8k32.row.col.f32.e4m3.e4m3.f32 "
                             "{%0,%1,%2,%3}, {%4,%5,%6,%7}, {%8,%9}, {%0,%1,%2,%3};\n"
                             : "+f"(acc[1][0]), "+f"(acc[1][1]), "+f"(acc[1][2]), "+f"(acc[1][3])
                             : "r"(a0), "r"(a1), "r"(a2), "r"(a3), "r"(b2), "r"(b3));
            }
        }
        __syncthreads();   // all warps done reading bufs 0..3 before reuse

        // layer0: prefetch emb[t+1] now — lands during dep compute + next cell
        if (!l1 && tid == 0 && (t + 1) < S_)
            issue4(&mE, (t + 1) * 32, btAddr, mbAddr, 0);

        // ---- dependent K-half: bufs 4..7 ----
        #pragma unroll
        for (int i = 0; i < 4; ++i) {
            mbar_wait(mbAddr + (4 + i) * 8, par);
            const int cc = l1 ? i : (4 + i);
            const unsigned aA   = aBase + cc * 256;
            const unsigned bufB = btAddr + (4 + i) * 8192 + rowOff;
            #pragma unroll
            for (int p = 0; p < 8; ++p) {
                unsigned a0, a1, a2, a3;
                asm volatile("ldmatrix.sync.aligned.m8n8.x4.shared.b16 {%0,%1,%2,%3}, [%4];\n"
                             : "=r"(a0), "=r"(a1), "=r"(a2), "=r"(a3) : "r"(aA + p * 32));
                const unsigned tt = 2u * p + k16;
                const unsigned bA = bufB + (tt >> 3) * 4096 + ((tt & 7) ^ xorv) * 16;
                unsigned b0, b1, b2, b3;
                asm volatile("ldmatrix.sync.aligned.m8n8.x4.shared.b16 {%0,%1,%2,%3}, [%4];\n"
                             : "=r"(b0), "=r"(b1), "=r"(b2), "=r"(b3) : "r"(bA));
                asm volatile("mma.sync.aligned.m16n8k32.row.col.f32.e4m3.e4m3.f32 "
                             "{%0,%1,%2,%3}, {%4,%5,%6,%7}, {%8,%9}, {%0,%1,%2,%3};\n"
                             : "+f"(acc[0][0]), "+f"(acc[0][1]), "+f"(acc[0][2]), "+f"(acc[0][3])
                             : "r"(a0), "r"(a1), "r"(a2), "r"(a3), "r"(b0), "r"(b1));
                asm volatile("mma.sync.aligned.m16n8k32.row.col.f32.e4m3.e4m3.f32 "
                             "{%0,%1,%2,%3}, {%4,%5,%6,%7}, {%8,%9}, {%0,%1,%2,%3};\n"
                             : "+f"(acc[1][0]), "+f"(acc[1][1]), "+f"(acc[1][2]), "+f"(acc[1][3])
                             : "r"(a0), "r"(a1), "r"(a2), "r"(a3), "r"(b2), "r"(b3));
            }
        }

        // ---- stage z ----
        {
            const int r  = lane >> 2;
            const int cb = nh * 16 + ((lane & 3) << 1);
            #pragma unroll
            for (int nt = 0; nt < 2; ++nt) {
                S->z[g][r][cb + nt * 8]         = acc[nt][0];
                S->z[g][r][cb + nt * 8 + 1]     = acc[nt][1];
                S->z[g][r + 8][cb + nt * 8]     = acc[nt][2];
                S->z[g][r + 8][cb + nt * 8 + 1] = acc[nt][3];
            }
        }
        __syncthreads();

        // ---- LSTM cell (fp32; 1/1024 undoes x16 weight, x64 act scales) ----
        #pragma unroll
        for (int j = 0; j < 2; ++j) {
            const int b = bb + j;
            float zi = S->z[0][u_loc][b] * 0.0009765625f + bi;
            float zf = S->z[1][u_loc][b] * 0.0009765625f + bf_;
            float zg = S->z[2][u_loc][b] * 0.0009765625f + bg_;
            float zo = S->z[3][u_loc][b] * 0.0009765625f + bo_;
            float ig = 1.f / (1.f + __expf(-zi));
            float fg = 1.f / (1.f + __expf(-zf));
            float og = 1.f / (1.f + __expf(-zo));
            float gc = tanhf(zg);
            c_st[j] = fg * c_st[j] + ig * gc;
            float h = og * tanhf(c_st[j]);
            S->hst[b][u_loc] =
                (unsigned char)__nv_cvt_float_to_fp8(h * 64.f, __NV_SATFINITE, __NV_E4M3);
        }
        __syncthreads();

        // ---- coalesced h store + release ----
        if (tid < 32) {
            unsigned char* dst = hout + (size_t)(t + 1) * HSLOT + tid * H_ + cg * 16;
            *reinterpret_cast<uint4*>(dst) = *reinterpret_cast<const uint4*>(&S->hst[tid][0]);
            __threadfence();
        }
        __syncthreads();
        if (tid == 0) st_rel(myFlag, (unsigned)(t + 1));
    }
}

// ----------------------------- FC + softmax ---------------------------------
__global__ void fc_kernel(const float* __restrict__ Wfc, const float* __restrict__ bfc,
                          float* __restrict__ out) {
    __shared__ float hs[32][129];
    const int tidx = threadIdx.x;
    const int v = blockIdx.x * 256 + tidx;
    float acc[32];
    #pragma unroll
    for (int b = 0; b < 32; ++b) acc[b] = 0.f;

    const unsigned char* __restrict__ h1 = g_h1 + (size_t)S_ * HSLOT;
    for (int kt = 0; kt < 8; ++kt) {
        __syncthreads();
        for (int e = tidx; e < 32 * 128; e += 256) {
            int b = e >> 7, kk = e & 127;
            float hv = (float)(*reinterpret_cast<const __nv_fp8_e4m3*>(
                &h1[b * H_ + kt * 128 + kk]));
            hs[b][kk] = hv * 0.015625f;
        }
        __syncthreads();
        const float* w2 = Wfc + (size_t)(kt * 128) * V_ + v;
        #pragma unroll 4
        for (int kk = 0; kk < 128; ++kk) {
            float wv = w2[(size_t)kk * V_];
            #pragma unroll
            for (int b = 0; b < 32; ++b) acc[b] += hs[b][kk] * wv;
        }
    }
    const float bv = bfc[v];
    #pragma unroll
    for (int b = 0; b < 32; ++b) out[(size_t)b * V_ + v] = acc[b] + bv;
}

__global__ void softmax_kernel(float* __restrict__ out) {
    float* row = out + (size_t)blockIdx.x * V_;
    __shared__ float sd[32];
    const int tid = threadIdx.x;

    float m = -3.4e38f;
    for (int v = tid; v < V_; v += 256) m = fmaxf(m, row[v]);
    #pragma unroll
    for (int o = 16; o; o >>= 1) m = fmaxf(m, __shfl_xor_sync(0xffffffffu, m, o));
    if ((tid & 31) == 0) sd[tid >> 5] = m;
    __syncthreads();
    if (tid == 0) {
        float mm = sd[0];
        for (int i = 1; i < 8; ++i) mm = fmaxf(mm, sd[i]);
        sd[16] = mm;
    }
    __syncthreads();
    m = sd[16];

    float s = 0.f;
    for (int v = tid; v < V_; v += 256) s += expf(row[v] - m);
    #pragma unroll
    for (int o = 16; o; o >>= 1) s += __shfl_xor_sync(0xffffffffu, s, o);
    if ((tid & 31) == 0) sd[tid >> 5] = s;
    __syncthreads();
    if (tid == 0) {
        float ss = 0.f;
        for (int i = 0; i < 8; ++i) ss += sd[i];
        sd[17] = ss;
    }
    __syncthreads();
    const float inv = 1.f / sd[17];
    for (int v = tid; v < V_; v += 256) row[v] = expf(row[v] - m) * inv;
}

// ------------------------------- launch --------------------------------------
typedef CUresult (CUDAAPI *tmap_fn_t)(CUtensorMap*, CUtensorMapDataType, cuuint32_t,
                                      void*, const cuuint64_t*, const cuuint64_t*,
                                      const cuuint32_t*, const cuuint32_t*,
                                      CUtensorMapInterleave, CUtensorMapSwizzle,
                                      CUtensorMapL2promotion, CUtensorMapFloatOOBfill);

static void make_map(tmap_fn_t fn, CUtensorMap* m, void* base, unsigned long long rows) {
    cuuint64_t dims[2]    = {1024ull, rows};
    cuuint64_t strides[1] = {1024ull};
    cuuint32_t box[2]     = {128u, 32u};
    cuuint32_t es[2]      = {1u, 1u};
    fn(m, CU_TENSOR_MAP_DATA_TYPE_UINT8, 2, base, dims, strides, box, es,
       CU_TENSOR_MAP_INTERLEAVE_NONE, CU_TENSOR_MAP_SWIZZLE_128B,
       CU_TENSOR_MAP_L2_PROMOTION_L2_128B, CU_TENSOR_MAP_FLOAT_OOB_FILL_NONE);
}

extern "C" void kernel_launch(void* const* d_in, const int* in_sizes, int n_in,
                              void* d_out, int out_size) {
    const int*   x   = (const int*)d_in[0];
    const float* emb = (const float*)d_in[1];
    const float* Wx0 = (const float*)d_in[2];
    const float* Wh0 = (const float*)d_in[3];
    const float* b0  = (const float*)d_in[4];
    const float* Wx1 = (const float*)d_in[5];
    const float* Wh1 = (const float*)d_in[6];
    const float* b1  = (const float*)d_in[7];
    const float* Wfc = (const float*)d_in[8];
    const float* bfc = (const float*)d_in[9];
    float* out = (float*)d_out;

    tmap_fn_t fn = nullptr;
    cudaDriverEntryPointQueryResult st;
    cudaGetDriverEntryPointByVersion("cuTensorMapEncodeTiled", (void**)&fn, 12050,
                                     cudaEnableDefault, &st);
    void *pE = nullptr, *pH0 = nullptr, *pH1 = nullptr;
    cudaGetSymbolAddress(&pE, g_emb);
    cudaGetSymbolAddress(&pH0, g_h0);
    cudaGetSymbolAddress(&pH1, g_h1);
    CUtensorMap mE, mH0, mH1;
    make_map(fn, &mE, pE, (unsigned long long)S_ * 32ull);
    make_map(fn, &mH0, pH0, (unsigned long long)(S_ + 1) * 32ull);
    make_map(fn, &mH1, pH1, (unsigned long long)(S_ + 1) * 32ull);

    cudaFuncSetAttribute(lstm_persistent,
                         cudaFuncAttributeMaxDynamicSharedMemorySize, (int)sizeof(Sm));

    prep_weights<<<2048, 256>>>(Wx0, Wh0, 0);
    prep_weights<<<2048, 256>>>(Wx1, Wh1, 1);
    prep_embed<<<2048, 256>>>(x, emb);
    prep_init<<<64, 256>>>();
    lstm_persistent<<<128, 256, sizeof(Sm)>>>(mE, mH0, mH1, b0, b1);
    fc_kernel<<<125, 256>>>(Wfc, bfc, out);
    softmax_kernel<<<32, 256>>>(out);
}

// round 12
// speedup vs baseline: 2.0427x; 2.0427x over previous
#include <cuda_runtime.h>
#include <cuda.h>
#include <cuda_fp16.h>
#include <cuda_fp8.h>

// 2-layer LSTM LM, B=32,S=512,H=1024,V=32000.
// fp8 weights resident in smem; fp8 activations via TMA.
// Both layers: weight chunks 0-3 = input-x (indep), 4-7 = own-h (dep).
// Indep bufs prefetched one step ahead; dep TMA issued at step start by tid0
// and hidden under indep compute. Single release counter per layer.
#define B_   32
#define S_   512
#define H_   1024
#define V_   32000
#define GPL  64
#define HSLOT 32768

__device__ unsigned char g_W0[(size_t)4096 * 2048];       // fp8 e4m3 x16, [r][k]
__device__ unsigned char g_W1[(size_t)4096 * 2048];
__device__ unsigned char g_emb[(size_t)S_ * HSLOT];       // fp8 x64, [t*32+b][k]
__device__ unsigned char g_h0[(size_t)(S_ + 1) * HSLOT];  // fp8 x64
__device__ unsigned char g_h1[(size_t)(S_ + 1) * HSLOT];
__device__ unsigned g_cnt0;
__device__ unsigned g_cnt1;

struct Sm {
    unsigned char A[64][2064];       // 132096 B resident fp8 weights
    unsigned char Bt[8][8192];       //  65536 B: 8 chunk buffers (2 SW128 boxes each)
    float         z[4][16][36];      //   9216 B gate staging
    unsigned char hst[32][16];       //    512 B h staging
    unsigned long long mbar[8];
};                                   // 207424 B -> 1 CTA/SM

// ------------------------------ helpers -------------------------------------
__device__ __forceinline__ unsigned smem_u32(const void* p) {
    return (unsigned)__cvta_generic_to_shared(p);
}
__device__ __forceinline__ void cp16(void* dst, const void* src) {
    unsigned d = smem_u32(dst);
    asm volatile("cp.async.cg.shared.global [%0], [%1], 16;\n" :: "r"(d), "l"(src) : "memory");
}
__device__ __forceinline__ unsigned ld_acq(const unsigned* p) {
    unsigned v;
    asm volatile("ld.acquire.gpu.global.u32 %0, [%1];" : "=r"(v) : "l"(p) : "memory");
    return v;
}
__device__ __forceinline__ void mbar_init(unsigned a, unsigned c) {
    asm volatile("mbarrier.init.shared.b64 [%0], %1;" :: "r"(a), "r"(c) : "memory");
}
__device__ __forceinline__ void mbar_expect(unsigned a, unsigned bytes) {
    asm volatile("mbarrier.arrive.expect_tx.shared.b64 _, [%0], %1;" :: "r"(a), "r"(bytes) : "memory");
}
__device__ __forceinline__ void mbar_wait(unsigned a, unsigned ph) {
    asm volatile(
        "{\n\t.reg .pred P;\n"
        "W%=:\n\t"
        "mbarrier.try_wait.parity.acquire.cta.shared::cta.b64 P, [%0], %1, 0x989680;\n\t"
        "@!P bra W%=;\n\t}"
        :: "r"(a), "r"(ph) : "memory");
}
__device__ __forceinline__ void tma2d(unsigned dst, const CUtensorMap* m, int x, int y,
                                      unsigned mb) {
    asm volatile(
        "cp.async.bulk.tensor.2d.shared::cta.global.tile.mbarrier::complete_tx::bytes "
        "[%0], [%1, {%2, %3}], [%4];"
        :: "r"(dst), "l"(m), "r"(x), "r"(y), "r"(mb) : "memory");
}
// issue 4 chunks (one K-half) into bufs [bufBase..bufBase+3]
__device__ __forceinline__ void issue4(const CUtensorMap* m, int y, unsigned btAddr,
                                       unsigned mbAddr, int bufBase) {
    #pragma unroll
    for (int i = 0; i < 4; ++i) {
        const unsigned mb = mbAddr + (unsigned)(bufBase + i) * 8;
        mbar_expect(mb, 8192u);
        const unsigned d = btAddr + (unsigned)(bufBase + i) * 8192;
        const int x = i * 256;
        tma2d(d, m, x, y, mb);
        tma2d(d + 4096, m, x + 128, y, mb);
    }
}
__device__ __forceinline__ void spin_ge(const unsigned* p, unsigned tgt) {
    while (ld_acq(p) < tgt) __nanosleep(16);
}

// ------------------------------- prep ---------------------------------------
__global__ void prep_weights(const float* __restrict__ Wx, const float* __restrict__ Wh,
                             int layer) {
    unsigned char* __restrict__ W = layer ? g_W1 : g_W0;
    const size_t n = (size_t)4096 * 2048;
    for (size_t idx = (size_t)blockIdx.x * blockDim.x + threadIdx.x; idx < n;
         idx += (size_t)gridDim.x * blockDim.x) {
        int r = (int)(idx >> 11);
        int k = (int)(idx & 2047);
        int cgp = r >> 6, rem = r & 63;
        int gate = rem >> 4, uu = rem & 15;
        int j = gate * H_ + cgp * 16 + uu;
        float v = (k < H_) ? Wx[(size_t)k * 4096 + j]
                           : Wh[(size_t)(k - H_) * 4096 + j];
        W[idx] = (unsigned char)__nv_cvt_float_to_fp8(v * 16.f, __NV_SATFINITE, __NV_E4M3);
    }
}

__global__ void prep_embed(const int* __restrict__ x, const float* __restrict__ emb) {
    const size_t n = (size_t)S_ * HSLOT;
    for (size_t idx = (size_t)blockIdx.x * blockDim.x + threadIdx.x; idx < n;
         idx += (size_t)gridDim.x * blockDim.x) {
        int t   = (int)(idx >> 15);
        int rem = (int)(idx & 32767);
        int b   = rem >> 10;
        int k   = rem & 1023;
        float v = emb[(size_t)x[b * S_ + t] * H_ + k];
        g_emb[idx] = (unsigned char)__nv_cvt_float_to_fp8(v * 64.f, __NV_SATFINITE, __NV_E4M3);
    }
}

__global__ void prep_init() {
    for (int i = blockIdx.x * blockDim.x + threadIdx.x; i < HSLOT;
         i += gridDim.x * blockDim.x) {
        g_h0[i] = 0;
        g_h1[i] = 0;
    }
    if (blockIdx.x == 0 && threadIdx.x == 0) { g_cnt0 = 0u; g_cnt1 = 0u; }
}

// --------------------------- persistent LSTM --------------------------------
__global__ void __launch_bounds__(256, 1)
lstm_persistent(const __grid_constant__ CUtensorMap mE,
                const __grid_constant__ CUtensorMap mH0,
                const __grid_constant__ CUtensorMap mH1,
                const float* __restrict__ bias0, const float* __restrict__ bias1) {
    extern __shared__ __align__(1024) char smem_raw[];
    Sm* S = reinterpret_cast<Sm*>(smem_raw);

    const int tid  = threadIdx.x;
    const int lane = tid & 31;
    const int w    = tid >> 5;
    const int g    = w >> 1;                 // gate 0..3
    const int nh   = w & 1;                  // batch half
    const bool l1  = (blockIdx.x >= GPL);
    const int cg   = l1 ? (blockIdx.x - GPL) : blockIdx.x;

    const unsigned char* __restrict__ Wg = (l1 ? g_W1 : g_W0) + (size_t)cg * 64 * 2048;
    const float* __restrict__ bias = l1 ? bias1 : bias0;
    unsigned char* hout = l1 ? g_h1 : g_h0;
    unsigned* myCnt  = l1 ? &g_cnt1 : &g_cnt0;
    unsigned* ownCnt = myCnt;

    // ---- resident fp8 weights (once) ----
    #pragma unroll
    for (int m = 0; m < 32; ++m) {
        int u   = tid + (m << 8);
        int row = u >> 7;
        int off = (u & 127) << 4;
        cp16(&S->A[row][off], Wg + (size_t)row * 2048 + off);
    }
    asm volatile("cp.async.commit_group;\ncp.async.wait_group 0;\n" ::: "memory");

    const unsigned mbAddr = smem_u32(&S->mbar[0]);
    const unsigned btAddr = smem_u32(&S->Bt[0][0]);
    if (tid == 0) {
        #pragma unroll
        for (int i = 0; i < 8; ++i) mbar_init(mbAddr + i * 8, 1);
    }
    asm volatile("fence.proxy.async.shared::cta;" ::: "memory");
    __syncthreads();

    // ---- A ldmatrix addressing (fp8 m16n8k32 fragments) ----
    const unsigned aBase = smem_u32(
        &S->A[g * 16 + ((lane >> 3) & 1) * 8 + (lane & 7)][(lane >> 4) * 16]);
    // ---- B (activations, SW128 boxes [32 rows][128 cols]) ----
    const int b_row = nh * 16 + ((lane >> 4) & 1) * 8 + (lane & 7);
    const unsigned k16  = (lane >> 3) & 1;
    const unsigned xorv = (unsigned)(b_row & 7);
    const unsigned rowOff = (unsigned)b_row * 128;

    // ---- cell ownership ----
    const int u_loc = tid >> 4;
    const int u_g   = cg * 16 + u_loc;
    const int bb    = (tid & 15) << 1;
    const float bi  = bias[u_g];
    const float bf_ = bias[H_ + u_g];
    const float bg_ = bias[2 * H_ + u_g];
    const float bo_ = bias[3 * H_ + u_g];
    float c_st[2] = {0.f, 0.f};

    // ---- prologue: prefetch indep bufs 0-3 for step 0 ----
    if (tid == 0) {
        if (!l1) {
            issue4(&mE, 0, btAddr, mbAddr, 0);            // emb[0]
        } else {
            spin_ge(&g_cnt0, 64u);                        // h0[1] ready
            issue4(&mH0, 32, btAddr, mbAddr, 0);
        }
    }

    for (int t = 0; t < S_; ++t) {
        const unsigned par = (unsigned)t & 1u;

        // ---- dep TMA: own h[t]; tid0 polls own-layer counter, others proceed ----
        if (tid == 0) {
            spin_ge(ownCnt, 64u * (unsigned)t);
            issue4(l1 ? &mH1 : &mH0, t * 32, btAddr, mbAddr, 4);
        }

        float acc[2][4] = {{0.f, 0.f, 0.f, 0.f}, {0.f, 0.f, 0.f, 0.f}};

        // ---- independent K-half: bufs 0..3 (prefetched), weight chunks 0..3 ----
        #pragma unroll
        for (int i = 0; i < 4; ++i) {
            mbar_wait(mbAddr + i * 8, par);
            const unsigned aA   = aBase + i * 256;
            const unsigned bufB = btAddr + i * 8192 + rowOff;
            #pragma unroll
            for (int p = 0; p < 8; ++p) {
                unsigned a0, a1, a2, a3;
                asm volatile("ldmatrix.sync.aligned.m8n8.x4.shared.b16 {%0,%1,%2,%3}, [%4];\n"
                             : "=r"(a0), "=r"(a1), "=r"(a2), "=r"(a3) : "r"(aA + p * 32));
                const unsigned tt = 2u * p + k16;
                const unsigned bA = bufB + (tt >> 3) * 4096 + ((tt & 7) ^ xorv) * 16;
                unsigned b0, b1, b2, b3;
                asm volatile("ldmatrix.sync.aligned.m8n8.x4.shared.b16 {%0,%1,%2,%3}, [%4];\n"
                             : "=r"(b0), "=r"(b1), "=r"(b2), "=r"(b3) : "r"(bA));
                asm volatile("mma.sync.aligned.m16n8k32.row.col.f32.e4m3.e4m3.f32 "
                             "{%0,%1,%2,%3}, {%4,%5,%6,%7}, {%8,%9}, {%0,%1,%2,%3};\n"
                             : "+f"(acc[0][0]), "+f"(acc[0][1]), "+f"(acc[0][2]), "+f"(acc[0][3])
                             : "r"(a0), "r"(a1), "r"(a2), "r"(a3), "r"(b0), "r"(b1));
                asm volatile("mma.sync.aligned.m16n8k32.row.col.f32.e4m3.e4m3.f32 "
                             "{%0,%1,%2,%3}, {%4,%5,%6,%7}, {%8,%9}, {%0,%1,%2,%3};\n"
                             : "+f"(acc[1][0]), "+f"(acc[1][1]), "+f"(acc[1][2]), "+f"(acc[1][3])
                             : "r"(a0), "r"(a1), "r"(a2), "r"(a3), "r"(b2), "r"(b3));
            }
        }
        __syncthreads();   // bufs 0..3 free for next-step prefetch

        // ---- prefetch next step's indep bufs (hidden under dep compute) ----
        if (tid == 0 && (t + 1) < S_) {
            if (!l1) {
                issue4(&mE, (t + 1) * 32, btAddr, mbAddr, 0);      // emb[t+1]
            } else {
                spin_ge(&g_cnt0, 64u * (unsigned)(t + 2));         // h0[t+2]
                issue4(&mH0, (t + 2) * 32, btAddr, mbAddr, 0);
            }
        }

        // ---- dependent K-half: bufs 4..7, weight chunks 4..7 ----
        #pragma unroll
        for (int i = 0; i < 4; ++i) {
            mbar_wait(mbAddr + (4 + i) * 8, par);
            const unsigned aA   = aBase + (4 + i) * 256;
            const unsigned bufB = btAddr + (4 + i) * 8192 + rowOff;
            #pragma unroll
            for (int p = 0; p < 8; ++p) {
                unsigned a0, a1, a2, a3;
                asm volatile("ldmatrix.sync.aligned.m8n8.x4.shared.b16 {%0,%1,%2,%3}, [%4];\n"
                             : "=r"(a0), "=r"(a1), "=r"(a2), "=r"(a3) : "r"(aA + p * 32));
                const unsigned tt = 2u * p + k16;
                const unsigned bA = bufB + (tt >> 3) * 4096 + ((tt & 7) ^ xorv) * 16;
                unsigned b0, b1, b2, b3;
                asm volatile("ldmatrix.sync.aligned.m8n8.x4.shared.b16 {%0,%1,%2,%3}, [%4];\n"
                             : "=r"(b0), "=r"(b1), "=r"(b2), "=r"(b3) : "r"(bA));
                asm volatile("mma.sync.aligned.m16n8k32.row.col.f32.e4m3.e4m3.f32 "
                             "{%0,%1,%2,%3}, {%4,%5,%6,%7}, {%8,%9}, {%0,%1,%2,%3};\n"
                             : "+f"(acc[0][0]), "+f"(acc[0][1]), "+f"(acc[0][2]), "+f"(acc[0][3])
                             : "r"(a0), "r"(a1), "r"(a2), "r"(a3), "r"(b0), "r"(b1));
                asm volatile("mma.sync.aligned.m16n8k32.row.col.f32.e4m3.e4m3.f32 "
                             "{%0,%1,%2,%3}, {%4,%5,%6,%7}, {%8,%9}, {%0,%1,%2,%3};\n"
                             : "+f"(acc[1][0]), "+f"(acc[1][1]), "+f"(acc[1][2]), "+f"(acc[1][3])
                             : "r"(a0), "r"(a1), "r"(a2), "r"(a3), "r"(b2), "r"(b3));
            }
        }

        // ---- stage z ----
        {
            const int r  = lane >> 2;
            const int cb = nh * 16 + ((lane & 3) << 1);
            #pragma unroll
            for (int nt = 0; nt < 2; ++nt) {
                S->z[g][r][cb + nt * 8]         = acc[nt][0];
                S->z[g][r][cb + nt * 8 + 1]     = acc[nt][1];
                S->z[g][r + 8][cb + nt * 8]     = acc[nt][2];
                S->z[g][r + 8][cb + nt * 8 + 1] = acc[nt][3];
            }
        }
        __syncthreads();

        // ---- LSTM cell (fp32; 1/1024 undoes x16 weight, x64 act scales) ----
        #pragma unroll
        for (int j = 0; j < 2; ++j) {
            const int b = bb + j;
            float zi = S->z[0][u_loc][b] * 0.0009765625f + bi;
            float zf = S->z[1][u_loc][b] * 0.0009765625f + bf_;
            float zg = S->z[2][u_loc][b] * 0.0009765625f + bg_;
            float zo = S->z[3][u_loc][b] * 0.0009765625f + bo_;
            float ig = 1.f / (1.f + __expf(-zi));
            float fg = 1.f / (1.f + __expf(-zf));
            float og = 1.f / (1.f + __expf(-zo));
            float gc = tanhf(zg);
            c_st[j] = fg * c_st[j] + ig * gc;
            float h = og * tanhf(c_st[j]);
            S->hst[b][u_loc] =
                (unsigned char)__nv_cvt_float_to_fp8(h * 64.f, __NV_SATFINITE, __NV_E4M3);
        }
        __syncthreads();

        // ---- coalesced h store + release ----
        if (tid < 32) {
            unsigned char* dst = hout + (size_t)(t + 1) * HSLOT + tid * H_ + cg * 16;
            *reinterpret_cast<uint4*>(dst) = *reinterpret_cast<const uint4*>(&S->hst[tid][0]);
        }
        __threadfence();
        __syncthreads();
        if (tid == 0) atomicAdd(myCnt, 1u);
    }
}

// ----------------------------- FC + softmax ---------------------------------
__global__ void fc_kernel(const float* __restrict__ Wfc, const float* __restrict__ bfc,
                          float* __restrict__ out) {
    __shared__ float hs[32][129];
    const int tidx = threadIdx.x;
    const int v = blockIdx.x * 256 + tidx;
    float acc[32];
    #pragma unroll
    for (int b = 0; b < 32; ++b) acc[b] = 0.f;

    const unsigned char* __restrict__ h1 = g_h1 + (size_t)S_ * HSLOT;
    for (int kt = 0; kt < 8; ++kt) {
        __syncthreads();
        for (int e = tidx; e < 32 * 128; e += 256) {
            int b = e >> 7, kk = e & 127;
            float hv = (float)(*reinterpret_cast<const __nv_fp8_e4m3*>(
                &h1[b * H_ + kt * 128 + kk]));
            hs[b][kk] = hv * 0.015625f;
        }
        __syncthreads();
        const float* w2 = Wfc + (size_t)(kt * 128) * V_ + v;
        #pragma unroll 4
        for (int kk = 0; kk < 128; ++kk) {
            float wv = w2[(size_t)kk * V_];
            #pragma unroll
            for (int b = 0; b < 32; ++b) acc[b] += hs[b][kk] * wv;
        }
    }
    const float bv = bfc[v];
    #pragma unroll
    for (int b = 0; b < 32; ++b) out[(size_t)b * V_ + v] = acc[b] + bv;
}

__global__ void softmax_kernel(float* __restrict__ out) {
    float* row = out + (size_t)blockIdx.x * V_;
    __shared__ float sd[32];
    const int tid = threadIdx.x;

    float m = -3.4e38f;
    for (int v = tid; v < V_; v += 256) m = fmaxf(m, row[v]);
    #pragma unroll
    for (int o = 16; o; o >>= 1) m = fmaxf(m, __shfl_xor_sync(0xffffffffu, m, o));
    if ((tid & 31) == 0) sd[tid >> 5] = m;
    __syncthreads();
    if (tid == 0) {
        float mm = sd[0];
        for (int i = 1; i < 8; ++i) mm = fmaxf(mm, sd[i]);
        sd[16] = mm;
    }
    __syncthreads();
    m = sd[16];

    float s = 0.f;
    for (int v = tid; v < V_; v += 256) s += expf(row[v] - m);
    #pragma unroll
    for (int o = 16; o; o >>= 1) s += __shfl_xor_sync(0xffffffffu, s, o);
    if ((tid & 31) == 0) sd[tid >> 5] = s;
    __syncthreads();
    if (tid == 0) {
        float ss = 0.f;
        for (int i = 0; i < 8; ++i) ss += sd[i];
        sd[17] = ss;
    }
    __syncthreads();
    const float inv = 1.f / sd[17];
    for (int v = tid; v < V_; v += 256) row[v] = expf(row[v] - m) * inv;
}

// ------------------------------- launch --------------------------------------
typedef CUresult (CUDAAPI *tmap_fn_t)(CUtensorMap*, CUtensorMapDataType, cuuint32_t,
                                      void*, const cuuint64_t*, const cuuint64_t*,
                                      const cuuint32_t*, const cuuint32_t*,
                                      CUtensorMapInterleave, CUtensorMapSwizzle,
                                      CUtensorMapL2promotion, CUtensorMapFloatOOBfill);

static void make_map(tmap_fn_t fn, CUtensorMap* m, void* base, unsigned long long rows) {
    cuuint64_t dims[2]    = {1024ull, rows};
    cuuint64_t strides[1] = {1024ull};
    cuuint32_t box[2]     = {128u, 32u};
    cuuint32_t es[2]      = {1u, 1u};
    fn(m, CU_TENSOR_MAP_DATA_TYPE_UINT8, 2, base, dims, strides, box, es,
       CU_TENSOR_MAP_INTERLEAVE_NONE, CU_TENSOR_MAP_SWIZZLE_128B,
       CU_TENSOR_MAP_L2_PROMOTION_L2_128B, CU_TENSOR_MAP_FLOAT_OOB_FILL_NONE);
}

extern "C" void kernel_launch(void* const* d_in, const int* in_sizes, int n_in,
                              void* d_out, int out_size) {
    const int*   x   = (const int*)d_in[0];
    const float* emb = (const float*)d_in[1];
    const float* Wx0 = (const float*)d_in[2];
    const float* Wh0 = (const float*)d_in[3];
    const float* b0  = (const float*)d_in[4];
    const float* Wx1 = (const float*)d_in[5];
    const float* Wh1 = (const float*)d_in[6];
    const float* b1  = (const float*)d_in[7];
    const float* Wfc = (const float*)d_in[8];
    const float* bfc = (const float*)d_in[9];
    float* out = (float*)d_out;

    tmap_fn_t fn = nullptr;
    cudaDriverEntryPointQueryResult st;
    cudaGetDriverEntryPointByVersion("cuTensorMapEncodeTiled", (void**)&fn, 12050,
                                     cudaEnableDefault, &st);
    void *pE = nullptr, *pH0 = nullptr, *pH1 = nullptr;
    cudaGetSymbolAddress(&pE, g_emb);
    cudaGetSymbolAddress(&pH0, g_h0);
    cudaGetSymbolAddress(&pH1, g_h1);
    CUtensorMap mE, mH0, mH1;
    make_map(fn, &mE, pE, (unsigned long long)S_ * 32ull);
    make_map(fn, &mH0, pH0, (unsigned long long)(S_ + 1) * 32ull);
    make_map(fn, &mH1, pH1, (unsigned long long)(S_ + 1) * 32ull);

    cudaFuncSetAttribute(lstm_persistent,
                         cudaFuncAttributeMaxDynamicSharedMemorySize, (int)sizeof(Sm));

    prep_weights<<<2048, 256>>>(Wx0, Wh0, 0);
    prep_weights<<<2048, 256>>>(Wx1, Wh1, 1);
    prep_embed<<<2048, 256>>>(x, emb);
    prep_init<<<64, 256>>>();
    lstm_persistent<<<128, 256, sizeof(Sm)>>>(mE, mH0, mH1, b0, b1);
    fc_kernel<<<125, 256>>>(Wfc, bfc, out);
    softmax_kernel<<<32, 256>>>(out);
}

// round 13
// speedup vs baseline: 2.2851x; 1.1187x over previous
#include <cuda_runtime.h>
#include <cuda.h>
#include <cuda_fp16.h>
#include <cuda_fp8.h>

// 2-layer LSTM LM, B=32,S=512,H=1024,V=32000.
// fp8 weights resident in smem; fp8 activations via TMA.
// Weight chunks 0-3 = input-x (indep), 4-7 = own-h (dep).
// Indep bufs prefetched one step ahead (split named barrier, no convoy);
// dep TMA issued by warp 7 at step start, hidden under indep compute.
#define B_   32
#define S_   512
#define H_   1024
#define V_   32000
#define GPL  64
#define HSLOT 32768

__device__ unsigned char g_W0[(size_t)4096 * 2048];       // fp8 e4m3 x16, [r][k]
__device__ unsigned char g_W1[(size_t)4096 * 2048];
__device__ unsigned char g_emb[(size_t)S_ * HSLOT];       // fp8 x64, [t*32+b][k]
__device__ unsigned char g_h0[(size_t)(S_ + 1) * HSLOT];  // fp8 x64
__device__ unsigned char g_h1[(size_t)(S_ + 1) * HSLOT];
__device__ unsigned g_cnt0;
__device__ unsigned g_cnt1;

struct Sm {
    unsigned char A[64][2064];       // 132096 B resident fp8 weights
    unsigned char Bt[8][8192];       //  65536 B: 8 chunk buffers (2 SW128 boxes each)
    float         z[4][16][36];      //   9216 B gate staging
    unsigned char hst[32][16];       //    512 B h staging
    unsigned long long mbar[8];
};                                   // 207424 B -> 1 CTA/SM

// ------------------------------ helpers -------------------------------------
__device__ __forceinline__ unsigned smem_u32(const void* p) {
    return (unsigned)__cvta_generic_to_shared(p);
}
__device__ __forceinline__ void cp16(void* dst, const void* src) {
    unsigned d = smem_u32(dst);
    asm volatile("cp.async.cg.shared.global [%0], [%1], 16;\n" :: "r"(d), "l"(src) : "memory");
}
__device__ __forceinline__ unsigned ld_acq(const unsigned* p) {
    unsigned v;
    asm volatile("ld.acquire.gpu.global.u32 %0, [%1];" : "=r"(v) : "l"(p) : "memory");
    return v;
}
__device__ __forceinline__ void red_release(unsigned* p) {
    asm volatile("red.add.release.gpu.global.u32 [%0], 1;" :: "l"(p) : "memory");
}
__device__ __forceinline__ float tanhx(float x) {
    float y;
    asm("tanh.approx.f32 %0, %1;" : "=f"(y) : "f"(x));
    return y;
}
__device__ __forceinline__ void mbar_init(unsigned a, unsigned c) {
    asm volatile("mbarrier.init.shared.b64 [%0], %1;" :: "r"(a), "r"(c) : "memory");
}
__device__ __forceinline__ void mbar_expect(unsigned a, unsigned bytes) {
    asm volatile("mbarrier.arrive.expect_tx.shared.b64 _, [%0], %1;" :: "r"(a), "r"(bytes) : "memory");
}
__device__ __forceinline__ void mbar_wait(unsigned a, unsigned ph) {
    asm volatile(
        "{\n\t.reg .pred P;\n"
        "W%=:\n\t"
        "mbarrier.try_wait.parity.acquire.cta.shared::cta.b64 P, [%0], %1, 0x989680;\n\t"
        "@!P bra W%=;\n\t}"
        :: "r"(a), "r"(ph) : "memory");
}
__device__ __forceinline__ void tma2d(unsigned dst, const CUtensorMap* m, int x, int y,
                                      unsigned mb) {
    asm volatile(
        "cp.async.bulk.tensor.2d.shared::cta.global.tile.mbarrier::complete_tx::bytes "
        "[%0], [%1, {%2, %3}], [%4];"
        :: "r"(dst), "l"(m), "r"(x), "r"(y), "r"(mb) : "memory");
}
// issue 4 chunks (one K-half) into bufs [bufBase..bufBase+3]
__device__ __forceinline__ void issue4(const CUtensorMap* m, int y, unsigned btAddr,
                                       unsigned mbAddr, int bufBase) {
    #pragma unroll
    for (int i = 0; i < 4; ++i) {
        const unsigned mb = mbAddr + (unsigned)(bufBase + i) * 8;
        mbar_expect(mb, 8192u);
        const unsigned d = btAddr + (unsigned)(bufBase + i) * 8192;
        const int x = i * 256;
        tma2d(d, m, x, y, mb);
        tma2d(d + 4096, m, x + 128, y, mb);
    }
}
__device__ __forceinline__ void spin_ge(const unsigned* p, unsigned tgt) {
    while (ld_acq(p) < tgt) __nanosleep(16);
}

// ------------------------------- prep ---------------------------------------
__global__ void prep_weights(const float* __restrict__ Wx, const float* __restrict__ Wh,
                             int layer) {
    unsigned char* __restrict__ W = layer ? g_W1 : g_W0;
    const size_t n = (size_t)4096 * 2048;
    for (size_t idx = (size_t)blockIdx.x * blockDim.x + threadIdx.x; idx < n;
         idx += (size_t)gridDim.x * blockDim.x) {
        int r = (int)(idx >> 11);
        int k = (int)(idx & 2047);
        int cgp = r >> 6, rem = r & 63;
        int gate = rem >> 4, uu = rem & 15;
        int j = gate * H_ + cgp * 16 + uu;
        float v = (k < H_) ? Wx[(size_t)k * 4096 + j]
                           : Wh[(size_t)(k - H_) * 4096 + j];
        W[idx] = (unsigned char)__nv_cvt_float_to_fp8(v * 16.f, __NV_SATFINITE, __NV_E4M3);
    }
}

__global__ void prep_embed(const int* __restrict__ x, const float* __restrict__ emb) {
    const size_t n = (size_t)S_ * HSLOT;
    for (size_t idx = (size_t)blockIdx.x * blockDim.x + threadIdx.x; idx < n;
         idx += (size_t)gridDim.x * blockDim.x) {
        int t   = (int)(idx >> 15);
        int rem = (int)(idx & 32767);
        int b   = rem >> 10;
        int k   = rem & 1023;
        float v = emb[(size_t)x[b * S_ + t] * H_ + k];
        g_emb[idx] = (unsigned char)__nv_cvt_float_to_fp8(v * 64.f, __NV_SATFINITE, __NV_E4M3);
    }
}

__global__ void prep_init() {
    for (int i = blockIdx.x * blockDim.x + threadIdx.x; i < HSLOT;
         i += gridDim.x * blockDim.x) {
        g_h0[i] = 0;
        g_h1[i] = 0;
    }
    if (blockIdx.x == 0 && threadIdx.x == 0) { g_cnt0 = 0u; g_cnt1 = 0u; }
}

// --------------------------- persistent LSTM --------------------------------
__global__ void __launch_bounds__(256, 1)
lstm_persistent(const __grid_constant__ CUtensorMap mE,
                const __grid_constant__ CUtensorMap mH0,
                const __grid_constant__ CUtensorMap mH1,
                const float* __restrict__ bias0, const float* __restrict__ bias1) {
    extern __shared__ __align__(1024) char smem_raw[];
    Sm* S = reinterpret_cast<Sm*>(smem_raw);

    const int tid  = threadIdx.x;
    const int lane = tid & 31;
    const int w    = tid >> 5;
    const int g    = w >> 1;                 // gate 0..3
    const int nh   = w & 1;                  // batch half
    const bool l1  = (blockIdx.x >= GPL);
    const int cg   = l1 ? (blockIdx.x - GPL) : blockIdx.x;

    const unsigned char* __restrict__ Wg = (l1 ? g_W1 : g_W0) + (size_t)cg * 64 * 2048;
    const float* __restrict__ bias = l1 ? bias1 : bias0;
    unsigned char* hout = l1 ? g_h1 : g_h0;
    unsigned* myCnt  = l1 ? &g_cnt1 : &g_cnt0;

    // ---- resident fp8 weights (once) ----
    #pragma unroll
    for (int m = 0; m < 32; ++m) {
        int u   = tid + (m << 8);
        int row = u >> 7;
        int off = (u & 127) << 4;
        cp16(&S->A[row][off], Wg + (size_t)row * 2048 + off);
    }
    asm volatile("cp.async.commit_group;\ncp.async.wait_group 0;\n" ::: "memory");

    const unsigned mbAddr = smem_u32(&S->mbar[0]);
    const unsigned btAddr = smem_u32(&S->Bt[0][0]);
    if (tid == 0) {
        #pragma unroll
        for (int i = 0; i < 8; ++i) mbar_init(mbAddr + i * 8, 1);
    }
    asm volatile("fence.proxy.async.shared::cta;" ::: "memory");
    __syncthreads();

    // ---- A ldmatrix addressing (fp8 m16n8k32 fragments) ----
    const unsigned aBase = smem_u32(
        &S->A[g * 16 + ((lane >> 3) & 1) * 8 + (lane & 7)][(lane >> 4) * 16]);
    // ---- B (activations, SW128 boxes [32 rows][128 cols]) ----
    const int b_row = nh * 16 + ((lane >> 4) & 1) * 8 + (lane & 7);
    const unsigned k16  = (lane >> 3) & 1;
    const unsigned xorv = (unsigned)(b_row & 7);
    const unsigned rowOff = (unsigned)b_row * 128;

    // ---- cell ownership ----
    const int u_loc = tid >> 4;
    const int u_g   = cg * 16 + u_loc;
    const int bb    = (tid & 15) << 1;
    const float bi  = bias[u_g];
    const float bf_ = bias[H_ + u_g];
    const float bg_ = bias[2 * H_ + u_g];
    const float bo_ = bias[3 * H_ + u_g];
    float c_st[2] = {0.f, 0.f};

    // ---- prologue: prefetch indep bufs 0-3 for step 0 ----
    if (tid == 0) {
        if (!l1) {
            issue4(&mE, 0, btAddr, mbAddr, 0);            // emb[0]
        } else {
            spin_ge(&g_cnt0, 64u);                        // h0[1] ready
            issue4(&mH0, 32, btAddr, mbAddr, 0);
        }
    }

    for (int t = 0; t < S_; ++t) {
        const unsigned par = (unsigned)t & 1u;

        // ---- dep TMA: own h[t]; warp 7's lane 0 spins, other warps proceed ----
        if (tid == 224) {
            spin_ge(myCnt, 64u * (unsigned)t);
            issue4(l1 ? &mH1 : &mH0, t * 32, btAddr, mbAddr, 4);
        }

        float acc[2][4] = {{0.f, 0.f, 0.f, 0.f}, {0.f, 0.f, 0.f, 0.f}};

        // ---- independent K-half: bufs 0..3 (prefetched), weight chunks 0..3 ----
        #pragma unroll
        for (int i = 0; i < 4; ++i) {
            mbar_wait(mbAddr + i * 8, par);
            const unsigned aA   = aBase + i * 256;
            const unsigned bufB = btAddr + i * 8192 + rowOff;
            #pragma unroll
            for (int p = 0; p < 8; ++p) {
                unsigned a0, a1, a2, a3;
                asm volatile("ldmatrix.sync.aligned.m8n8.x4.shared.b16 {%0,%1,%2,%3}, [%4];\n"
                             : "=r"(a0), "=r"(a1), "=r"(a2), "=r"(a3) : "r"(aA + p * 32));
                const unsigned tt = 2u * p + k16;
                const unsigned bA = bufB + (tt >> 3) * 4096 + ((tt & 7) ^ xorv) * 16;
                unsigned b0, b1, b2, b3;
                asm volatile("ldmatrix.sync.aligned.m8n8.x4.shared.b16 {%0,%1,%2,%3}, [%4];\n"
                             : "=r"(b0), "=r"(b1), "=r"(b2), "=r"(b3) : "r"(bA));
                asm volatile("mma.sync.aligned.m16n8k32.row.col.f32.e4m3.e4m3.f32 "
                             "{%0,%1,%2,%3}, {%4,%5,%6,%7}, {%8,%9}, {%0,%1,%2,%3};\n"
                             : "+f"(acc[0][0]), "+f"(acc[0][1]), "+f"(acc[0][2]), "+f"(acc[0][3])
                             : "r"(a0), "r"(a1), "r"(a2), "r"(a3), "r"(b0), "r"(b1));
                asm volatile("mma.sync.aligned.m16n8k32.row.col.f32.e4m3.e4m3.f32 "
                             "{%0,%1,%2,%3}, {%4,%5,%6,%7}, {%8,%9}, {%0,%1,%2,%3};\n"
                             : "+f"(acc[1][0]), "+f"(acc[1][1]), "+f"(acc[1][2]), "+f"(acc[1][3])
                             : "r"(a0), "r"(a1), "r"(a2), "r"(a3), "r"(b2), "r"(b3));
            }
        }

        // ---- split barrier: warps 1-7 flow into dep compute; warp 0 waits,
        //      then reissues indep bufs for step t+1 (bufs 0..3 now free) ----
        if (w == 0) {
            asm volatile("bar.sync 1, 256;" ::: "memory");
            if (tid == 0 && (t + 1) < S_) {
                if (!l1) {
                    issue4(&mE, (t + 1) * 32, btAddr, mbAddr, 0);      // emb[t+1]
                } else {
                    spin_ge(&g_cnt0, 64u * (unsigned)(t + 2));         // h0[t+2]
                    issue4(&mH0, (t + 2) * 32, btAddr, mbAddr, 0);
                }
            }
        } else {
            asm volatile("bar.arrive 1, 256;" ::: "memory");
        }

        // ---- dependent K-half: bufs 4..7, weight chunks 4..7 ----
        #pragma unroll
        for (int i = 0; i < 4; ++i) {
            mbar_wait(mbAddr + (4 + i) * 8, par);
            const unsigned aA   = aBase + (4 + i) * 256;
            const unsigned bufB = btAddr + (4 + i) * 8192 + rowOff;
            #pragma unroll
            for (int p = 0; p < 8; ++p) {
                unsigned a0, a1, a2, a3;
                asm volatile("ldmatrix.sync.aligned.m8n8.x4.shared.b16 {%0,%1,%2,%3}, [%4];\n"
                             : "=r"(a0), "=r"(a1), "=r"(a2), "=r"(a3) : "r"(aA + p * 32));
                const unsigned tt = 2u * p + k16;
                const unsigned bA = bufB + (tt >> 3) * 4096 + ((tt & 7) ^ xorv) * 16;
                unsigned b0, b1, b2, b3;
                asm volatile("ldmatrix.sync.aligned.m8n8.x4.shared.b16 {%0,%1,%2,%3}, [%4];\n"
                             : "=r"(b0), "=r"(b1), "=r"(b2), "=r"(b3) : "r"(bA));
                asm volatile("mma.sync.aligned.m16n8k32.row.col.f32.e4m3.e4m3.f32 "
                             "{%0,%1,%2,%3}, {%4,%5,%6,%7}, {%8,%9}, {%0,%1,%2,%3};\n"
                             : "+f"(acc[0][0]), "+f"(acc[0][1]), "+f"(acc[0][2]), "+f"(acc[0][3])
                             : "r"(a0), "r"(a1), "r"(a2), "r"(a3), "r"(b0), "r"(b1));
                asm volatile("mma.sync.aligned.m16n8k32.row.col.f32.e4m3.e4m3.f32 "
                             "{%0,%1,%2,%3}, {%4,%5,%6,%7}, {%8,%9}, {%0,%1,%2,%3};\n"
                             : "+f"(acc[1][0]), "+f"(acc[1][1]), "+f"(acc[1][2]), "+f"(acc[1][3])
                             : "r"(a0), "r"(a1), "r"(a2), "r"(a3), "r"(b2), "r"(b3));
            }
        }

        // ---- stage z ----
        {
            const int r  = lane >> 2;
            const int cb = nh * 16 + ((lane & 3) << 1);
            #pragma unroll
            for (int nt = 0; nt < 2; ++nt) {
                S->z[g][r][cb + nt * 8]         = acc[nt][0];
                S->z[g][r][cb + nt * 8 + 1]     = acc[nt][1];
                S->z[g][r + 8][cb + nt * 8]     = acc[nt][2];
                S->z[g][r + 8][cb + nt * 8 + 1] = acc[nt][3];
            }
        }
        __syncthreads();

        // ---- LSTM cell (fp32, MUFU.TANH; 1/1024 undoes x16 wt, x64 act scales) ----
        #pragma unroll
        for (int j = 0; j < 2; ++j) {
            const int b = bb + j;
            float zi = S->z[0][u_loc][b] * 0.0009765625f + bi;
            float zf = S->z[1][u_loc][b] * 0.0009765625f + bf_;
            float zg = S->z[2][u_loc][b] * 0.0009765625f + bg_;
            float zo = S->z[3][u_loc][b] * 0.0009765625f + bo_;
            float ig = fmaf(0.5f, tanhx(0.5f * zi), 0.5f);
            float fg = fmaf(0.5f, tanhx(0.5f * zf), 0.5f);
            float og = fmaf(0.5f, tanhx(0.5f * zo), 0.5f);
            float gc = tanhx(zg);
            c_st[j] = fg * c_st[j] + ig * gc;
            float h = og * tanhx(c_st[j]);
            S->hst[b][u_loc] =
                (unsigned char)__nv_cvt_float_to_fp8(h * 64.f, __NV_SATFINITE, __NV_E4M3);
        }
        __syncthreads();

        // ---- coalesced h store + release (release atomic publishes stores) ----
        if (tid < 32) {
            unsigned char* dst = hout + (size_t)(t + 1) * HSLOT + tid * H_ + cg * 16;
            *reinterpret_cast<uint4*>(dst) = *reinterpret_cast<const uint4*>(&S->hst[tid][0]);
        }
        __syncthreads();
        if (tid == 0) red_release(myCnt);
    }
}

// ----------------------------- FC + softmax ---------------------------------
__global__ void fc_kernel(const float* __restrict__ Wfc, const float* __restrict__ bfc,
                          float* __restrict__ out) {
    __shared__ float hs[32][129];
    const int tidx = threadIdx.x;
    const int v = blockIdx.x * 256 + tidx;
    float acc[32];
    #pragma unroll
    for (int b = 0; b < 32; ++b) acc[b] = 0.f;

    const unsigned char* __restrict__ h1 = g_h1 + (size_t)S_ * HSLOT;
    for (int kt = 0; kt < 8; ++kt) {
        __syncthreads();
        for (int e = tidx; e < 32 * 128; e += 256) {
            int b = e >> 7, kk = e & 127;
            float hv = (float)(*reinterpret_cast<const __nv_fp8_e4m3*>(
                &h1[b * H_ + kt * 128 + kk]));
            hs[b][kk] = hv * 0.015625f;
        }
        __syncthreads();
        const float* w2 = Wfc + (size_t)(kt * 128) * V_ + v;
        #pragma unroll 4
        for (int kk = 0; kk < 128; ++kk) {
            float wv = w2[(size_t)kk * V_];
            #pragma unroll
            for (int b = 0; b < 32; ++b) acc[b] += hs[b][kk] * wv;
        }
    }
    const float bv = bfc[v];
    #pragma unroll
    for (int b = 0; b < 32; ++b) out[(size_t)b * V_ + v] = acc[b] + bv;
}

__global__ void softmax_kernel(float* __restrict__ out) {
    float* row = out + (size_t)blockIdx.x * V_;
    __shared__ float sd[32];
    const int tid = threadIdx.x;

    float m = -3.4e38f;
    for (int v = tid; v < V_; v += 256) m = fmaxf(m, row[v]);
    #pragma unroll
    for (int o = 16; o; o >>= 1) m = fmaxf(m, __shfl_xor_sync(0xffffffffu, m, o));
    if ((tid & 31) == 0) sd[tid >> 5] = m;
    __syncthreads();
    if (tid == 0) {
        float mm = sd[0];
        for (int i = 1; i < 8; ++i) mm = fmaxf(mm, sd[i]);
        sd[16] = mm;
    }
    __syncthreads();
    m = sd[16];

    float s = 0.f;
    for (int v = tid; v < V_; v += 256) s += expf(row[v] - m);
    #pragma unroll
    for (int o = 16; o; o >>= 1) s += __shfl_xor_sync(0xffffffffu, s, o);
    if ((tid & 31) == 0) sd[tid >> 5] = s;
    __syncthreads();
    if (tid == 0) {
        float ss = 0.f;
        for (int i = 0; i < 8; ++i) ss += sd[i];
        sd[17] = ss;
    }
    __syncthreads();
    const float inv = 1.f / sd[17];
    for (int v = tid; v < V_; v += 256) row[v] = expf(row[v] - m) * inv;
}

// ------------------------------- launch --------------------------------------
typedef CUresult (CUDAAPI *tmap_fn_t)(CUtensorMap*, CUtensorMapDataType, cuuint32_t,
                                      void*, const cuuint64_t*, const cuuint64_t*,
                                      const cuuint32_t*, const cuuint32_t*,
                                      CUtensorMapInterleave, CUtensorMapSwizzle,
                                      CUtensorMapL2promotion, CUtensorMapFloatOOBfill);

static void make_map(tmap_fn_t fn, CUtensorMap* m, void* base, unsigned long long rows) {
    cuuint64_t dims[2]    = {1024ull, rows};
    cuuint64_t strides[1] = {1024ull};
    cuuint32_t box[2]     = {128u, 32u};
    cuuint32_t es[2]      = {1u, 1u};
    fn(m, CU_TENSOR_MAP_DATA_TYPE_UINT8, 2, base, dims, strides, box, es,
       CU_TENSOR_MAP_INTERLEAVE_NONE, CU_TENSOR_MAP_SWIZZLE_128B,
       CU_TENSOR_MAP_L2_PROMOTION_L2_128B, CU_TENSOR_MAP_FLOAT_OOB_FILL_NONE);
}

extern "C" void kernel_launch(void* const* d_in, const int* in_sizes, int n_in,
                              void* d_out, int out_size) {
    const int*   x   = (const int*)d_in[0];
    const float* emb = (const float*)d_in[1];
    const float* Wx0 = (const float*)d_in[2];
    const float* Wh0 = (const float*)d_in[3];
    const float* b0  = (const float*)d_in[4];
    const float* Wx1 = (const float*)d_in[5];
    const float* Wh1 = (const float*)d_in[6];
    const float* b1  = (const float*)d_in[7];
    const float* Wfc = (const float*)d_in[8];
    const float* bfc = (const float*)d_in[9];
    float* out = (float*)d_out;

    tmap_fn_t fn = nullptr;
    cudaDriverEntryPointQueryResult st;
    cudaGetDriverEntryPointByVersion("cuTensorMapEncodeTiled", (void**)&fn, 12050,
                                     cudaEnableDefault, &st);
    void *pE = nullptr, *pH0 = nullptr, *pH1 = nullptr;
    cudaGetSymbolAddress(&pE, g_emb);
    cudaGetSymbolAddress(&pH0, g_h0);
    cudaGetSymbolAddress(&pH1, g_h1);
    CUtensorMap mE, mH0, mH1;
    make_map(fn, &mE, pE, (unsigned long long)S_ * 32ull);
    make_map(fn, &mH0, pH0, (unsigned long long)(S_ + 1) * 32ull);
    make_map(fn, &mH1, pH1, (unsigned long long)(S_ + 1) * 32ull);

    cudaFuncSetAttribute(lstm_persistent,
                         cudaFuncAttributeMaxDynamicSharedMemorySize, (int)sizeof(Sm));

    prep_weights<<<2048, 256>>>(Wx0, Wh0, 0);
    prep_weights<<<2048, 256>>>(Wx1, Wh1, 1);
    prep_embed<<<2048, 256>>>(x, emb);
    prep_init<<<64, 256>>>();
    lstm_persistent<<<128, 256, sizeof(Sm)>>>(mE, mH0, mH1, b0, b1);
    fc_kernel<<<125, 256>>>(Wfc, bfc, out);
    softmax_kernel<<<32, 256>>>(out);
}

// round 14
// speedup vs baseline: 2.4535x; 1.0737x over previous
#include <cuda_runtime.h>
#include <cuda.h>
#include <cuda_fp16.h>
#include <cuda_fp8.h>

// 2-layer LSTM LM, B=32,S=512,H=1024,V=32000.
// fp8 weights resident in smem; fp8 activations via TMA.
// 16 warps: warp = (gate, batch-half, K-half); each warp's serial mma chain
// halved vs R12. Indep bufs prefetched one step ahead; dep TMA issued by
// warp 15 at step start, hidden under indep compute.
#define B_   32
#define S_   512
#define H_   1024
#define V_   32000
#define GPL  64
#define HSLOT 32768

__device__ unsigned char g_W0[(size_t)4096 * 2048];       // fp8 e4m3 x16, [r][k]
__device__ unsigned char g_W1[(size_t)4096 * 2048];
__device__ unsigned char g_emb[(size_t)S_ * HSLOT];       // fp8 x64, [t*32+b][k]
__device__ unsigned char g_h0[(size_t)(S_ + 1) * HSLOT];  // fp8 x64
__device__ unsigned char g_h1[(size_t)(S_ + 1) * HSLOT];
__device__ unsigned g_cnt0;
__device__ unsigned g_cnt1;

struct Sm {
    unsigned char A[64][2064];       // 132096 B resident fp8 weights
    unsigned char Bt[8][8192];       //  65536 B: 8 chunk buffers (2 SW128 boxes each)
    float         z2[2][4][16][36];  //  18432 B gate staging, 2 K-half partials
    unsigned char hst[32][16];       //    512 B h staging
    unsigned long long mbar[8];
};                                   // 216640 B -> 1 CTA/SM

// ------------------------------ helpers -------------------------------------
__device__ __forceinline__ unsigned smem_u32(const void* p) {
    return (unsigned)__cvta_generic_to_shared(p);
}
__device__ __forceinline__ void cp16(void* dst, const void* src) {
    unsigned d = smem_u32(dst);
    asm volatile("cp.async.cg.shared.global [%0], [%1], 16;\n" :: "r"(d), "l"(src) : "memory");
}
__device__ __forceinline__ unsigned ld_acq(const unsigned* p) {
    unsigned v;
    asm volatile("ld.acquire.gpu.global.u32 %0, [%1];" : "=r"(v) : "l"(p) : "memory");
    return v;
}
__device__ __forceinline__ void red_release(unsigned* p) {
    asm volatile("red.add.release.gpu.global.u32 [%0], 1;" :: "l"(p) : "memory");
}
__device__ __forceinline__ float tanhx(float x) {
    float y;
    asm("tanh.approx.f32 %0, %1;" : "=f"(y) : "f"(x));
    return y;
}
__device__ __forceinline__ void mbar_init(unsigned a, unsigned c) {
    asm volatile("mbarrier.init.shared.b64 [%0], %1;" :: "r"(a), "r"(c) : "memory");
}
__device__ __forceinline__ void mbar_expect(unsigned a, unsigned bytes) {
    asm volatile("mbarrier.arrive.expect_tx.shared.b64 _, [%0], %1;" :: "r"(a), "r"(bytes) : "memory");
}
__device__ __forceinline__ void mbar_wait(unsigned a, unsigned ph) {
    asm volatile(
        "{\n\t.reg .pred P;\n"
        "W%=:\n\t"
        "mbarrier.try_wait.parity.acquire.cta.shared::cta.b64 P, [%0], %1, 0x989680;\n\t"
        "@!P bra W%=;\n\t}"
        :: "r"(a), "r"(ph) : "memory");
}
__device__ __forceinline__ void tma2d(unsigned dst, const CUtensorMap* m, int x, int y,
                                      unsigned mb) {
    asm volatile(
        "cp.async.bulk.tensor.2d.shared::cta.global.tile.mbarrier::complete_tx::bytes "
        "[%0], [%1, {%2, %3}], [%4];"
        :: "r"(dst), "l"(m), "r"(x), "r"(y), "r"(mb) : "memory");
}
// issue 4 chunks (one K-half) into bufs [bufBase..bufBase+3]
__device__ __forceinline__ void issue4(const CUtensorMap* m, int y, unsigned btAddr,
                                       unsigned mbAddr, int bufBase) {
    #pragma unroll
    for (int i = 0; i < 4; ++i) {
        const unsigned mb = mbAddr + (unsigned)(bufBase + i) * 8;
        mbar_expect(mb, 8192u);
        const unsigned d = btAddr + (unsigned)(bufBase + i) * 8192;
        const int x = i * 256;
        tma2d(d, m, x, y, mb);
        tma2d(d + 4096, m, x + 128, y, mb);
    }
}
__device__ __forceinline__ void spin_ge(const unsigned* p, unsigned tgt) {
    while (ld_acq(p) < tgt) __nanosleep(16);
}

// ------------------------------- prep ---------------------------------------
__global__ void prep_weights(const float* __restrict__ Wx, const float* __restrict__ Wh,
                             int layer) {
    unsigned char* __restrict__ W = layer ? g_W1 : g_W0;
    const size_t n = (size_t)4096 * 2048;
    for (size_t idx = (size_t)blockIdx.x * blockDim.x + threadIdx.x; idx < n;
         idx += (size_t)gridDim.x * blockDim.x) {
        int r = (int)(idx >> 11);
        int k = (int)(idx & 2047);
        int cgp = r >> 6, rem = r & 63;
        int gate = rem >> 4, uu = rem & 15;
        int j = gate * H_ + cgp * 16 + uu;
        float v = (k < H_) ? Wx[(size_t)k * 4096 + j]
                           : Wh[(size_t)(k - H_) * 4096 + j];
        W[idx] = (unsigned char)__nv_cvt_float_to_fp8(v * 16.f, __NV_SATFINITE, __NV_E4M3);
    }
}

__global__ void prep_embed(const int* __restrict__ x, const float* __restrict__ emb) {
    const size_t n = (size_t)S_ * HSLOT;
    for (size_t idx = (size_t)blockIdx.x * blockDim.x + threadIdx.x; idx < n;
         idx += (size_t)gridDim.x * blockDim.x) {
        int t   = (int)(idx >> 15);
        int rem = (int)(idx & 32767);
        int b   = rem >> 10;
        int k   = rem & 1023;
        float v = emb[(size_t)x[b * S_ + t] * H_ + k];
        g_emb[idx] = (unsigned char)__nv_cvt_float_to_fp8(v * 64.f, __NV_SATFINITE, __NV_E4M3);
    }
}

__global__ void prep_init() {
    for (int i = blockIdx.x * blockDim.x + threadIdx.x; i < HSLOT;
         i += gridDim.x * blockDim.x) {
        g_h0[i] = 0;
        g_h1[i] = 0;
    }
    if (blockIdx.x == 0 && threadIdx.x == 0) { g_cnt0 = 0u; g_cnt1 = 0u; }
}

// --------------------------- persistent LSTM --------------------------------
__global__ void __launch_bounds__(512, 1)
lstm_persistent(const __grid_constant__ CUtensorMap mE,
                const __grid_constant__ CUtensorMap mH0,
                const __grid_constant__ CUtensorMap mH1,
                const float* __restrict__ bias0, const float* __restrict__ bias1) {
    extern __shared__ __align__(1024) char smem_raw[];
    Sm* S = reinterpret_cast<Sm*>(smem_raw);

    const int tid  = threadIdx.x;
    const int lane = tid & 31;
    const int w    = tid >> 5;                // 0..15
    const int g    = w >> 2;                  // gate 0..3
    const int nh   = (w >> 1) & 1;            // batch half
    const int kh   = w & 1;                   // K half within each phase
    const bool l1  = (blockIdx.x >= GPL);
    const int cg   = l1 ? (blockIdx.x - GPL) : blockIdx.x;

    const unsigned char* __restrict__ Wg = (l1 ? g_W1 : g_W0) + (size_t)cg * 64 * 2048;
    const float* __restrict__ bias = l1 ? bias1 : bias0;
    unsigned char* hout = l1 ? g_h1 : g_h0;
    unsigned* myCnt  = l1 ? &g_cnt1 : &g_cnt0;

    // ---- resident fp8 weights (once) ----
    #pragma unroll
    for (int m = 0; m < 16; ++m) {
        int u   = tid + (m << 9);             // 0..8191 16B units
        int row = u >> 7;
        int off = (u & 127) << 4;
        cp16(&S->A[row][off], Wg + (size_t)row * 2048 + off);
    }
    asm volatile("cp.async.commit_group;\ncp.async.wait_group 0;\n" ::: "memory");

    const unsigned mbAddr = smem_u32(&S->mbar[0]);
    const unsigned btAddr = smem_u32(&S->Bt[0][0]);
    if (tid == 0) {
        #pragma unroll
        for (int i = 0; i < 8; ++i) mbar_init(mbAddr + i * 8, 1);
    }
    asm volatile("fence.proxy.async.shared::cta;" ::: "memory");
    __syncthreads();

    // ---- A ldmatrix addressing (fp8 m16n8k32 fragments) ----
    const unsigned aBase = smem_u32(
        &S->A[g * 16 + ((lane >> 3) & 1) * 8 + (lane & 7)][(lane >> 4) * 16]);
    // ---- B (activations, SW128 boxes [32 rows][128 cols]) ----
    const int b_row = nh * 16 + ((lane >> 4) & 1) * 8 + (lane & 7);
    const unsigned k16  = (lane >> 3) & 1;
    const unsigned xorv = (unsigned)(b_row & 7);
    const unsigned rowOff = (unsigned)b_row * 128;

    // ---- cell ownership: one (u, b) pair per thread ----
    const int u_loc = tid >> 5;               // 0..15
    const int u_g   = cg * 16 + u_loc;
    const int bc    = lane;                   // batch 0..31
    const float bi  = bias[u_g];
    const float bf_ = bias[H_ + u_g];
    const float bg_ = bias[2 * H_ + u_g];
    const float bo_ = bias[3 * H_ + u_g];
    float c_st = 0.f;

    // ---- prologue: prefetch indep bufs 0-3 for step 0 ----
    if (tid == 0) {
        if (!l1) {
            issue4(&mE, 0, btAddr, mbAddr, 0);            // emb[0]
        } else {
            spin_ge(&g_cnt0, 64u);                        // h0[1] ready
            issue4(&mH0, 32, btAddr, mbAddr, 0);
        }
    }

    for (int t = 0; t < S_; ++t) {
        const unsigned par = (unsigned)t & 1u;

        // ---- dep TMA: own h[t]; warp 15 lane 0 spins, other warps proceed ----
        if (tid == 480) {
            spin_ge(myCnt, 64u * (unsigned)t);
            issue4(l1 ? &mH1 : &mH0, t * 32, btAddr, mbAddr, 4);
        }

        float acc[2][4] = {{0.f, 0.f, 0.f, 0.f}, {0.f, 0.f, 0.f, 0.f}};

        // ---- independent K-half: this warp's 2 bufs (kh*2, kh*2+1) ----
        #pragma unroll
        for (int ii = 0; ii < 2; ++ii) {
            const int i = kh * 2 + ii;
            mbar_wait(mbAddr + i * 8, par);
            const unsigned aA   = aBase + i * 256;
            const unsigned bufB = btAddr + i * 8192 + rowOff;
            #pragma unroll
            for (int p = 0; p < 8; ++p) {
                unsigned a0, a1, a2, a3;
                asm volatile("ldmatrix.sync.aligned.m8n8.x4.shared.b16 {%0,%1,%2,%3}, [%4];\n"
                             : "=r"(a0), "=r"(a1), "=r"(a2), "=r"(a3) : "r"(aA + p * 32));
                const unsigned tt = 2u * p + k16;
                const unsigned bA = bufB + (tt >> 3) * 4096 + ((tt & 7) ^ xorv) * 16;
                unsigned b0, b1, b2, b3;
                asm volatile("ldmatrix.sync.aligned.m8n8.x4.shared.b16 {%0,%1,%2,%3}, [%4];\n"
                             : "=r"(b0), "=r"(b1), "=r"(b2), "=r"(b3) : "r"(bA));
                asm volatile("mma.sync.aligned.m16n8k32.row.col.f32.e4m3.e4m3.f32 "
                             "{%0,%1,%2,%3}, {%4,%5,%6,%7}, {%8,%9}, {%0,%1,%2,%3};\n"
                             : "+f"(acc[0][0]), "+f"(acc[0][1]), "+f"(acc[0][2]), "+f"(acc[0][3])
                             : "r"(a0), "r"(a1), "r"(a2), "r"(a3), "r"(b0), "r"(b1));
                asm volatile("mma.sync.aligned.m16n8k32.row.col.f32.e4m3.e4m3.f32 "
                             "{%0,%1,%2,%3}, {%4,%5,%6,%7}, {%8,%9}, {%0,%1,%2,%3};\n"
                             : "+f"(acc[1][0]), "+f"(acc[1][1]), "+f"(acc[1][2]), "+f"(acc[1][3])
                             : "r"(a0), "r"(a1), "r"(a2), "r"(a3), "r"(b2), "r"(b3));
            }
        }

        // ---- split barrier: warps 1-15 flow into dep compute; warp 0 waits,
        //      then reissues indep bufs for step t+1 (bufs 0..3 now free) ----
        if (w == 0) {
            asm volatile("bar.sync 1, 512;" ::: "memory");
            if (tid == 0 && (t + 1) < S_) {
                if (!l1) {
                    issue4(&mE, (t + 1) * 32, btAddr, mbAddr, 0);      // emb[t+1]
                } else {
                    spin_ge(&g_cnt0, 64u * (unsigned)(t + 2));         // h0[t+2]
                    issue4(&mH0, (t + 2) * 32, btAddr, mbAddr, 0);
                }
            }
        } else {
            asm volatile("bar.arrive 1, 512;" ::: "memory");
        }

        // ---- dependent K-half: this warp's 2 bufs (4+kh*2, 4+kh*2+1) ----
        #pragma unroll
        for (int ii = 0; ii < 2; ++ii) {
            const int i = 4 + kh * 2 + ii;
            mbar_wait(mbAddr + i * 8, par);
            const unsigned aA   = aBase + i * 256;
            const unsigned bufB = btAddr + i * 8192 + rowOff;
            #pragma unroll
            for (int p = 0; p < 8; ++p) {
                unsigned a0, a1, a2, a3;
                asm volatile("ldmatrix.sync.aligned.m8n8.x4.shared.b16 {%0,%1,%2,%3}, [%4];\n"
                             : "=r"(a0), "=r"(a1), "=r"(a2), "=r"(a3) : "r"(aA + p * 32));
                const unsigned tt = 2u * p + k16;
                const unsigned bA = bufB + (tt >> 3) * 4096 + ((tt & 7) ^ xorv) * 16;
                unsigned b0, b1, b2, b3;
                asm volatile("ldmatrix.sync.aligned.m8n8.x4.shared.b16 {%0,%1,%2,%3}, [%4];\n"
                             : "=r"(b0), "=r"(b1), "=r"(b2), "=r"(b3) : "r"(bA));
                asm volatile("mma.sync.aligned.m16n8k32.row.col.f32.e4m3.e4m3.f32 "
                             "{%0,%1,%2,%3}, {%4,%5,%6,%7}, {%8,%9}, {%0,%1,%2,%3};\n"
                             : "+f"(acc[0][0]), "+f"(acc[0][1]), "+f"(acc[0][2]), "+f"(acc[0][3])
                             : "r"(a0), "r"(a1), "r"(a2), "r"(a3), "r"(b0), "r"(b1));
                asm volatile("mma.sync.aligned.m16n8k32.row.col.f32.e4m3.e4m3.f32 "
                             "{%0,%1,%2,%3}, {%4,%5,%6,%7}, {%8,%9}, {%0,%1,%2,%3};\n"
                             : "+f"(acc[1][0]), "+f"(acc[1][1]), "+f"(acc[1][2]), "+f"(acc[1][3])
                             : "r"(a0), "r"(a1), "r"(a2), "r"(a3), "r"(b2), "r"(b3));
            }
        }

        // ---- stage z partials: z2[kh][g] ----
        {
            const int r  = lane >> 2;
            const int cb = nh * 16 + ((lane & 3) << 1);
            #pragma unroll
            for (int nt = 0; nt < 2; ++nt) {
                S->z2[kh][g][r][cb + nt * 8]         = acc[nt][0];
                S->z2[kh][g][r][cb + nt * 8 + 1]     = acc[nt][1];
                S->z2[kh][g][r + 8][cb + nt * 8]     = acc[nt][2];
                S->z2[kh][g][r + 8][cb + nt * 8 + 1] = acc[nt][3];
            }
        }
        __syncthreads();

        // ---- LSTM cell: one (u,b) per thread (fp32, MUFU.TANH) ----
        {
            float zi = (S->z2[0][0][u_loc][bc] + S->z2[1][0][u_loc][bc]) * 0.0009765625f + bi;
            float zf = (S->z2[0][1][u_loc][bc] + S->z2[1][1][u_loc][bc]) * 0.0009765625f + bf_;
            float zg = (S->z2[0][2][u_loc][bc] + S->z2[1][2][u_loc][bc]) * 0.0009765625f + bg_;
            float zo = (S->z2[0][3][u_loc][bc] + S->z2[1][3][u_loc][bc]) * 0.0009765625f + bo_;
            float ig = fmaf(0.5f, tanhx(0.5f * zi), 0.5f);
            float fg = fmaf(0.5f, tanhx(0.5f * zf), 0.5f);
            float og = fmaf(0.5f, tanhx(0.5f * zo), 0.5f);
            float gc = tanhx(zg);
            c_st = fg * c_st + ig * gc;
            float h = og * tanhx(c_st);
            S->hst[bc][u_loc] =
                (unsigned char)__nv_cvt_float_to_fp8(h * 64.f, __NV_SATFINITE, __NV_E4M3);
        }
        __syncthreads();

        // ---- coalesced h store + release (release atomic publishes stores) ----
        if (tid < 32) {
            unsigned char* dst = hout + (size_t)(t + 1) * HSLOT + tid * H_ + cg * 16;
            *reinterpret_cast<uint4*>(dst) = *reinterpret_cast<const uint4*>(&S->hst[tid][0]);
        }
        __syncthreads();
        if (tid == 0) red_release(myCnt);
    }
}

// ----------------------------- FC + softmax ---------------------------------
__global__ void fc_kernel(const float* __restrict__ Wfc, const float* __restrict__ bfc,
                          float* __restrict__ out) {
    __shared__ float hs[32][129];
    const int tidx = threadIdx.x;
    const int v = blockIdx.x * 256 + tidx;
    float acc[32];
    #pragma unroll
    for (int b = 0; b < 32; ++b) acc[b] = 0.f;

    const unsigned char* __restrict__ h1 = g_h1 + (size_t)S_ * HSLOT;
    for (int kt = 0; kt < 8; ++kt) {
        __syncthreads();
        for (int e = tidx; e < 32 * 128; e += 256) {
            int b = e >> 7, kk = e & 127;
            float hv = (float)(*reinterpret_cast<const __nv_fp8_e4m3*>(
                &h1[b * H_ + kt * 128 + kk]));
            hs[b][kk] = hv * 0.015625f;
        }
        __syncthreads();
        const float* w2 = Wfc + (size_t)(kt * 128) * V_ + v;
        #pragma unroll 4
        for (int kk = 0; kk < 128; ++kk) {
            float wv = w2[(size_t)kk * V_];
            #pragma unroll
            for (int b = 0; b < 32; ++b) acc[b] += hs[b][kk] * wv;
        }
    }
    const float bv = bfc[v];
    #pragma unroll
    for (int b = 0; b < 32; ++b) out[(size_t)b * V_ + v] = acc[b] + bv;
}

__global__ void softmax_kernel(float* __restrict__ out) {
    float* row = out + (size_t)blockIdx.x * V_;
    __shared__ float sd[32];
    const int tid = threadIdx.x;

    float m = -3.4e38f;
    for (int v = tid; v < V_; v += 256) m = fmaxf(m, row[v]);
    #pragma unroll
    for (int o = 16; o; o >>= 1) m = fmaxf(m, __shfl_xor_sync(0xffffffffu, m, o));
    if ((tid & 31) == 0) sd[tid >> 5] = m;
    __syncthreads();
    if (tid == 0) {
        float mm = sd[0];
        for (int i = 1; i < 8; ++i) mm = fmaxf(mm, sd[i]);
        sd[16] = mm;
    }
    __syncthreads();
    m = sd[16];

    float s = 0.f;
    for (int v = tid; v < V_; v += 256) s += expf(row[v] - m);
    #pragma unroll
    for (int o = 16; o; o >>= 1) s += __shfl_xor_sync(0xffffffffu, s, o);
    if ((tid & 31) == 0) sd[tid >> 5] = s;
    __syncthreads();
    if (tid == 0) {
        float ss = 0.f;
        for (int i = 0; i < 8; ++i) ss += sd[i];
        sd[17] = ss;
    }
    __syncthreads();
    const float inv = 1.f / sd[17];
    for (int v = tid; v < V_; v += 256) row[v] = expf(row[v] - m) * inv;
}

// ------------------------------- launch --------------------------------------
typedef CUresult (CUDAAPI *tmap_fn_t)(CUtensorMap*, CUtensorMapDataType, cuuint32_t,
                                      void*, const cuuint64_t*, const cuuint64_t*,
                                      const cuuint32_t*, const cuuint32_t*,
                                      CUtensorMapInterleave, CUtensorMapSwizzle,
                                      CUtensorMapL2promotion, CUtensorMapFloatOOBfill);

static void make_map(tmap_fn_t fn, CUtensorMap* m, void* base, unsigned long long rows) {
    cuuint64_t dims[2]    = {1024ull, rows};
    cuuint64_t strides[1] = {1024ull};
    cuuint32_t box[2]     = {128u, 32u};
    cuuint32_t es[2]      = {1u, 1u};
    fn(m, CU_TENSOR_MAP_DATA_TYPE_UINT8, 2, base, dims, strides, box, es,
       CU_TENSOR_MAP_INTERLEAVE_NONE, CU_TENSOR_MAP_SWIZZLE_128B,
       CU_TENSOR_MAP_L2_PROMOTION_L2_128B, CU_TENSOR_MAP_FLOAT_OOB_FILL_NONE);
}

extern "C" void kernel_launch(void* const* d_in, const int* in_sizes, int n_in,
                              void* d_out, int out_size) {
    const int*   x   = (const int*)d_in[0];
    const float* emb = (const float*)d_in[1];
    const float* Wx0 = (const float*)d_in[2];
    const float* Wh0 = (const float*)d_in[3];
    const float* b0  = (const float*)d_in[4];
    const float* Wx1 = (const float*)d_in[5];
    const float* Wh1 = (const float*)d_in[6];
    const float* b1  = (const float*)d_in[7];
    const float* Wfc = (const float*)d_in[8];
    const float* bfc = (const float*)d_in[9];
    float* out = (float*)d_out;

    tmap_fn_t fn = nullptr;
    cudaDriverEntryPointQueryResult st;
    cudaGetDriverEntryPointByVersion("cuTensorMapEncodeTiled", (void**)&fn, 12050,
                                     cudaEnableDefault, &st);
    void *pE = nullptr, *pH0 = nullptr, *pH1 = nullptr;
    cudaGetSymbolAddress(&pE, g_emb);
    cudaGetSymbolAddress(&pH0, g_h0);
    cudaGetSymbolAddress(&pH1, g_h1);
    CUtensorMap mE, mH0, mH1;
    make_map(fn, &mE, pE, (unsigned long long)S_ * 32ull);
    make_map(fn, &mH0, pH0, (unsigned long long)(S_ + 1) * 32ull);
    make_map(fn, &mH1, pH1, (unsigned long long)(S_ + 1) * 32ull);

    cudaFuncSetAttribute(lstm_persistent,
                         cudaFuncAttributeMaxDynamicSharedMemorySize, (int)sizeof(Sm));

    prep_weights<<<2048, 256>>>(Wx0, Wh0, 0);
    prep_weights<<<2048, 256>>>(Wx1, Wh1, 1);
    prep_embed<<<2048, 256>>>(x, emb);
    prep_init<<<64, 256>>>();
    lstm_persistent<<<128, 512, sizeof(Sm)>>>(mE, mH0, mH1, b0, b1);
    fc_kernel<<<125, 256>>>(Wfc, bfc, out);
    softmax_kernel<<<32, 256>>>(out);
}